// round 2
// baseline (speedup 1.0000x reference)
#include <cuda_runtime.h>
#include <cuda_bf16.h>
#include <stdint.h>

#define SPLITK 148
#define KCHUNK 64
#define LTOT   256
#define DDIM   128

// scratch (allocation-free rule: __device__ globals)
__device__ float g_p[200064];                       // exp(logits) per token
__device__ float g_part[SPLITK * LTOT * DDIM];      // split-K partial numerators
__device__ float g_zpart[SPLITK * LTOT];            // split-K partial denominators

// ---------------------------------------------------------------------------
// Kernel 1: p = exp(W2 . tanh(f @ W1 + b1) + b2), fp32 with packed f32x2 FMA
// block = 256 thr, tile = 128 tokens. thread = 4 tokens x 8 j (4 f32x2 pairs)
// ---------------------------------------------------------------------------
#define SM1_BYTES (128*132*4 + 128*64*4)

__global__ __launch_bounds__(256, 2) void k1_logits(
    const float* __restrict__ feats, const float* __restrict__ W1,
    const float* __restrict__ b1, const float* __restrict__ W2,
    const float* __restrict__ b2, int B)
{
    extern __shared__ float sm1[];
    float* fsm = sm1;              // [128][132] padded fp32
    float* w1s = sm1 + 128*132;    // [128 k][64 j]

    int tid = threadIdx.x;
    int tok0 = blockIdx.x * 128;

    #pragma unroll
    for (int i = 0; i < 8; i++) {
        int idx = tid + i*256;
        ((float4*)w1s)[idx] = ((const float4*)W1)[idx];
    }
    #pragma unroll
    for (int i = 0; i < 16; i++) {
        int idx = tid + i*256;
        int row = idx >> 5, c4 = idx & 31;
        int tok = tok0 + row;
        float4 v = make_float4(0.f, 0.f, 0.f, 0.f);
        if (tok < B) v = ((const float4*)(feats + (size_t)tok*DDIM))[c4];
        *((float4*)(fsm + row*132 + c4*4)) = v;
    }
    __syncthreads();

    int tx = tid & 7;       // j group: j = tx*8 .. tx*8+7
    int ty = tid >> 3;      // token quad: tokens ty*4 .. ty*4+3
    int j0 = tx * 8;

    unsigned long long acc[4][4];
    #pragma unroll
    for (int p = 0; p < 4; p++) {
        float lo = b1[j0 + 2*p], hi = b1[j0 + 2*p + 1];
        unsigned long long bb;
        asm("mov.b64 %0, {%1,%2};" : "=l"(bb) : "f"(lo), "f"(hi));
        #pragma unroll
        for (int q = 0; q < 4; q++) acc[q][p] = bb;
    }

    const float* frow = fsm + (ty*4)*132;
    #pragma unroll 4
    for (int k = 0; k < 128; k++) {
        unsigned long long w[4];
        #pragma unroll
        for (int p = 0; p < 4; p++)
            w[p] = *((const unsigned long long*)(w1s + k*64 + j0 + 2*p));
        #pragma unroll
        for (int q = 0; q < 4; q++) {
            float a = frow[q*132 + k];
            unsigned long long ap;
            asm("mov.b64 %0, {%1,%1};" : "=l"(ap) : "f"(a));
            #pragma unroll
            for (int p = 0; p < 4; p++)
                asm("fma.rn.f32x2 %0, %1, %2, %0;" : "+l"(acc[q][p]) : "l"(ap), "l"(w[p]));
        }
    }

    float part[4];
    #pragma unroll
    for (int q = 0; q < 4; q++) {
        float s = 0.f;
        #pragma unroll
        for (int p = 0; p < 4; p++) {
            float x0, x1;
            asm("mov.b64 {%0,%1}, %2;" : "=f"(x0), "=f"(x1) : "l"(acc[q][p]));
            s += tanhf(x0) * W2[j0 + 2*p] + tanhf(x1) * W2[j0 + 2*p + 1];
        }
        part[q] = s;
    }
    #pragma unroll
    for (int q = 0; q < 4; q++) {
        #pragma unroll
        for (int m = 1; m <= 4; m <<= 1)
            part[q] += __shfl_xor_sync(0xffffffffu, part[q], m);
    }
    if (tx == 0) {
        float bb2 = b2[0];
        #pragma unroll
        for (int q = 0; q < 4; q++) {
            int tok = tok0 + ty*4 + q;
            if (tok < B) g_p[tok] = expf(part[q] + bb2);
        }
    }
}

// ---------------------------------------------------------------------------
// Kernel 2: split-K bf16 MMA: num[l,d] = sum_b mask[l,b] * (p[b]*f[b,d])
// g split into hi/lo bf16 planes; mask exact in bf16. Z fused into staging.
// grid = (2 l-tiles) x SPLITK, block = 256 thr = 8 warps.
// warp tile = 32 l x 64 d. Deterministic partials, no atomics.
// ---------------------------------------------------------------------------
#define MA_STRIDE 72     // bf16 elems: 144B rows (conflict-free ldmatrix)
#define G_STRIDE  136    // bf16 elems: 272B rows
#define SM2_BYTES (128*MA_STRIDE*2 + 2*(64*G_STRIDE*2) + 2048*4)

__device__ __forceinline__ void ldsm_x4(uint32_t* r, uint32_t addr) {
    asm volatile("ldmatrix.sync.aligned.m8n8.x4.shared.b16 {%0,%1,%2,%3}, [%4];"
        : "=r"(r[0]), "=r"(r[1]), "=r"(r[2]), "=r"(r[3]) : "r"(addr));
}
__device__ __forceinline__ void ldsm_x4_t(uint32_t* r, uint32_t addr) {
    asm volatile("ldmatrix.sync.aligned.m8n8.x4.trans.shared.b16 {%0,%1,%2,%3}, [%4];"
        : "=r"(r[0]), "=r"(r[1]), "=r"(r[2]), "=r"(r[3]) : "r"(addr));
}
__device__ __forceinline__ void mma_bf16(float* c, const uint32_t* a, uint32_t b0, uint32_t b1) {
    asm volatile("mma.sync.aligned.m16n8k16.row.col.f32.bf16.bf16.f32 "
        "{%0,%1,%2,%3}, {%4,%5,%6,%7}, {%8,%9}, {%0,%1,%2,%3};"
        : "+f"(c[0]), "+f"(c[1]), "+f"(c[2]), "+f"(c[3])
        : "r"(a[0]), "r"(a[1]), "r"(a[2]), "r"(a[3]), "r"(b0), "r"(b1));
}

__global__ __launch_bounds__(256, 2) void k2_mma(
    const float* __restrict__ feats, const float* __restrict__ mask,
    int B, int chunksPerSplit)
{
    extern __shared__ char smraw[];
    __nv_bfloat16* mA = (__nv_bfloat16*)smraw;          // [128 l][72]
    __nv_bfloat16* gH = mA + 128*MA_STRIDE;             // [64 k][136]
    __nv_bfloat16* gL = gH + 64*G_STRIDE;               // [64 k][136]
    float*        zsm = (float*)(gL + 64*G_STRIDE);     // [2048]

    int tid  = threadIdx.x;
    int lt   = blockIdx.x;
    int y    = blockIdx.y;
    int l0   = lt * 128;
    int wid  = tid >> 5, lane = tid & 31;
    int wm   = wid & 3, wn = wid >> 2;

    float acc[2][8][4];
    #pragma unroll
    for (int mt = 0; mt < 2; mt++)
        #pragma unroll
        for (int nt = 0; nt < 8; nt++)
            #pragma unroll
            for (int e = 0; e < 4; e++) acc[mt][nt][e] = 0.f;
    float zacc8[8];
    #pragma unroll
    for (int i = 0; i < 8; i++) zacc8[i] = 0.f;

    uint32_t mA_s = (uint32_t)__cvta_generic_to_shared(mA);
    uint32_t gH_s = (uint32_t)__cvta_generic_to_shared(gH);
    uint32_t gL_s = (uint32_t)__cvta_generic_to_shared(gL);

    for (int c = 0; c < chunksPerSplit; c++) {
        int kbase = (y * chunksPerSplit + c) * KCHUNK;
        __syncthreads();   // smem free from previous iter's MMAs

        // ---- stage mask tile [128 l][64 k] fp32 -> bf16 + fused Z partial ----
        #pragma unroll
        for (int i = 0; i < 8; i++) {
            int idx = tid + i*256;
            int row = idx >> 4, c4 = idx & 15;
            int gk = kbase + c4*4;
            const float* mp = mask + (size_t)(l0 + row) * B + gk;
            float4 v = make_float4(0.f, 0.f, 0.f, 0.f);
            if (gk + 3 < B) v = *((const float4*)mp);
            else {
                if (gk   < B) v.x = mp[0];
                if (gk+1 < B) v.y = mp[1];
                if (gk+2 < B) v.z = mp[2];
                if (gk+3 < B) v.w = mp[3];
            }
            float p0 = (gk   < B) ? g_p[gk]   : 0.f;
            float p1 = (gk+1 < B) ? g_p[gk+1] : 0.f;
            float p2 = (gk+2 < B) ? g_p[gk+2] : 0.f;
            float p3 = (gk+3 < B) ? g_p[gk+3] : 0.f;
            zacc8[i] += v.x*p0 + v.y*p1 + v.z*p2 + v.w*p3;
            __nv_bfloat16* dst = mA + row*MA_STRIDE + c4*4;
            *(__nv_bfloat162*)(dst)     = __floats2bfloat162_rn(v.x, v.y);
            *(__nv_bfloat162*)(dst + 2) = __floats2bfloat162_rn(v.z, v.w);
        }

        // ---- stage g tiles: [64 k][128 d], g = p*f split hi/lo bf16 ----
        #pragma unroll
        for (int i = 0; i < 8; i++) {
            int idx = tid + i*256;
            int row = idx >> 5, c4 = idx & 31;
            int tok = kbase + row;
            float4 v = make_float4(0.f, 0.f, 0.f, 0.f);
            float pk = 0.f;
            if (tok < B) {
                v = ((const float4*)(feats + (size_t)tok*DDIM))[c4];
                pk = g_p[tok];
            }
            float gx = v.x*pk, gy = v.y*pk, gz = v.z*pk, gw = v.w*pk;
            __nv_bfloat16 hx = __float2bfloat16(gx), hy = __float2bfloat16(gy);
            __nv_bfloat16 hz = __float2bfloat16(gz), hw = __float2bfloat16(gw);
            __nv_bfloat16* dh = gH + row*G_STRIDE + c4*4;
            dh[0] = hx; dh[1] = hy; dh[2] = hz; dh[3] = hw;
            __nv_bfloat16* dl = gL + row*G_STRIDE + c4*4;
            dl[0] = __float2bfloat16(gx - __bfloat162float(hx));
            dl[1] = __float2bfloat16(gy - __bfloat162float(hy));
            dl[2] = __float2bfloat16(gz - __bfloat162float(hz));
            dl[3] = __float2bfloat16(gw - __bfloat162float(hw));
        }
        __syncthreads();

        // ---- MMA accumulation over this 64-k chunk ----
        #pragma unroll
        for (int ks = 0; ks < 4; ks++) {
            uint32_t a[2][4];
            #pragma unroll
            for (int mt = 0; mt < 2; mt++) {
                uint32_t addr = mA_s + (uint32_t)(((wm*32 + mt*16 + (lane & 15)) * MA_STRIDE
                                 + ks*16 + ((lane >> 4) << 3)) * 2);
                ldsm_x4(a[mt], addr);
            }
            #pragma unroll
            for (int pl = 0; pl < 2; pl++) {
                uint32_t base = pl ? gL_s : gH_s;
                #pragma unroll
                for (int np = 0; np < 4; np++) {
                    uint32_t b[4];
                    uint32_t addr = base + (uint32_t)(((ks*16 + (lane & 15)) * G_STRIDE
                                     + wn*64 + np*16 + ((lane >> 4) << 3)) * 2);
                    ldsm_x4_t(b, addr);
                    #pragma unroll
                    for (int mt = 0; mt < 2; mt++) {
                        mma_bf16(acc[mt][np*2],     a[mt], b[0], b[1]);
                        mma_bf16(acc[mt][np*2 + 1], a[mt], b[2], b[3]);
                    }
                }
            }
        }
    }

    // ---- deterministic Z reduction ----
    __syncthreads();
    #pragma unroll
    for (int i = 0; i < 8; i++) zsm[tid + i*256] = zacc8[i];
    __syncthreads();
    if (tid < 128) {
        float z = 0.f;
        #pragma unroll
        for (int j = 0; j < 16; j++) z += zsm[tid*16 + j];
        g_zpart[y*LTOT + l0 + tid] = z;
    }

    // ---- write numerator partials ----
    #pragma unroll
    for (int mt = 0; mt < 2; mt++) {
        #pragma unroll
        for (int nt = 0; nt < 8; nt++) {
            int grow = l0 + wm*32 + mt*16 + (lane >> 2);
            int gcol = wn*64 + nt*8 + (lane & 3)*2;
            size_t b0 = ((size_t)y*LTOT + grow) * DDIM + gcol;
            size_t b1 = ((size_t)y*LTOT + grow + 8) * DDIM + gcol;
            *(float2*)(g_part + b0) = make_float2(acc[mt][nt][0], acc[mt][nt][1]);
            *(float2*)(g_part + b1) = make_float2(acc[mt][nt][2], acc[mt][nt][3]);
        }
    }
}

// ---------------------------------------------------------------------------
// Kernel 3: reduce split-K partials, divide by Z, zero empty libraries
// ---------------------------------------------------------------------------
__global__ void k3_reduce(float* __restrict__ out)
{
    int l = blockIdx.x, d = threadIdx.x;
    float num = 0.f, z = 0.f;
    #pragma unroll 4
    for (int y = 0; y < SPLITK; y++) {
        num += g_part[((size_t)y*LTOT + l) * DDIM + d];
        z   += g_zpart[y*LTOT + l];
    }
    out[l*DDIM + d] = (z > 0.f) ? num / z : 0.f;
}

// ---------------------------------------------------------------------------
extern "C" void kernel_launch(void* const* d_in, const int* in_sizes, int n_in,
                              void* d_out, int out_size)
{
    const float* feats = (const float*)d_in[0];
    const float* mask  = (const float*)d_in[1];
    const float* W1    = (const float*)d_in[2];
    const float* b1    = (const float*)d_in[3];
    const float* W2    = (const float*)d_in[4];
    const float* b2    = (const float*)d_in[5];
    float* out = (float*)d_out;

    int B = in_sizes[0] / DDIM;           // 200000
    int totalChunks = (B + KCHUNK - 1) / KCHUNK;
    int cps = (totalChunks + SPLITK - 1) / SPLITK;

    cudaFuncSetAttribute(k1_logits, cudaFuncAttributeMaxDynamicSharedMemorySize, SM1_BYTES);
    cudaFuncSetAttribute(k2_mma,    cudaFuncAttributeMaxDynamicSharedMemorySize, SM2_BYTES);

    int g1 = (B + 127) / 128;
    k1_logits<<<g1, 256, SM1_BYTES>>>(feats, W1, b1, W2, b2, B);

    dim3 g2(LTOT / 128, SPLITK);
    k2_mma<<<g2, 256, SM2_BYTES>>>(feats, mask, B, cps);

    k3_reduce<<<LTOT, DDIM>>>(out);
}

// round 3
// speedup vs baseline: 1.8603x; 1.8603x over previous
#include <cuda_runtime.h>
#include <cuda_bf16.h>
#include <stdint.h>

#define SPLITK 148
#define KCHUNK 64
#define LTOT   256
#define DDIM   128

// scratch (allocation-free rule: __device__ globals)
__device__ float g_p[200064];                       // exp(logits) per token
__device__ float g_part[SPLITK * LTOT * DDIM];      // split-K partial numerators
__device__ float g_zpart[SPLITK * LTOT];            // split-K partial denominators

// ---------------------------------------------------------------------------
// common MMA helpers (validated in round 1)
// ---------------------------------------------------------------------------
__device__ __forceinline__ void ldsm_x4(uint32_t* r, uint32_t addr) {
    asm volatile("ldmatrix.sync.aligned.m8n8.x4.shared.b16 {%0,%1,%2,%3}, [%4];"
        : "=r"(r[0]), "=r"(r[1]), "=r"(r[2]), "=r"(r[3]) : "r"(addr));
}
__device__ __forceinline__ void ldsm_x4_t(uint32_t* r, uint32_t addr) {
    asm volatile("ldmatrix.sync.aligned.m8n8.x4.trans.shared.b16 {%0,%1,%2,%3}, [%4];"
        : "=r"(r[0]), "=r"(r[1]), "=r"(r[2]), "=r"(r[3]) : "r"(addr));
}
__device__ __forceinline__ void mma_bf16(float* c, const uint32_t* a, uint32_t b0, uint32_t b1) {
    asm volatile("mma.sync.aligned.m16n8k16.row.col.f32.bf16.bf16.f32 "
        "{%0,%1,%2,%3}, {%4,%5,%6,%7}, {%8,%9}, {%0,%1,%2,%3};"
        : "+f"(c[0]), "+f"(c[1]), "+f"(c[2]), "+f"(c[3])
        : "r"(a[0]), "r"(a[1]), "r"(a[2]), "r"(a[3]), "r"(b0), "r"(b1));
}
__device__ __forceinline__ void split_bf16(float x, __nv_bfloat16& h, __nv_bfloat16& l) {
    h = __float2bfloat16(x);
    l = __float2bfloat16(x - __bfloat162float(h));
}

// ---------------------------------------------------------------------------
// Kernel 1: p = exp(W2 . tanh(f @ W1 + b1) + b2) via bf16 tensor cores,
// 3-plane split (fh*wh + fh*wl + fl*wh). Block = 256 thr = 8 warps,
// tile = 128 tokens x 64 j, K=128 staged in two 64-k halves.
// ---------------------------------------------------------------------------
#define K1_STR 72
// aH(9216) aL(9216) wH(4608) wL(4608) bf16 elems
#define SM1_BYTES ((9216*2 + 4608*2) * 2)

__global__ __launch_bounds__(256, 2) void k1_logits(
    const float* __restrict__ feats, const float* __restrict__ W1,
    const float* __restrict__ b1, const float* __restrict__ W2,
    const float* __restrict__ b2, int B)
{
    extern __shared__ __nv_bfloat16 sm1[];
    __nv_bfloat16* aH = sm1;
    __nv_bfloat16* aL = sm1 + 9216;
    __nv_bfloat16* wH = sm1 + 18432;
    __nv_bfloat16* wL = sm1 + 23040;

    int tid = threadIdx.x;
    int tok0 = blockIdx.x * 128;
    int wid = tid >> 5, lane = tid & 31;

    uint32_t aH_s = (uint32_t)__cvta_generic_to_shared(aH);
    uint32_t aL_s = (uint32_t)__cvta_generic_to_shared(aL);
    uint32_t wH_s = (uint32_t)__cvta_generic_to_shared(wH);
    uint32_t wL_s = (uint32_t)__cvta_generic_to_shared(wL);

    float acc[8][4];
    #pragma unroll
    for (int nt = 0; nt < 8; nt++)
        #pragma unroll
        for (int e = 0; e < 4; e++) acc[nt][e] = 0.f;

    #pragma unroll
    for (int ks2 = 0; ks2 < 2; ks2++) {
        if (ks2) __syncthreads();  // smem free from previous half's MMAs

        // stage features [128 tok][64 k] fp32 -> hi/lo bf16
        #pragma unroll
        for (int i = 0; i < 8; i++) {
            int idx = tid + i*256;
            int row = idx >> 4, c4 = idx & 15;
            int tok = tok0 + row;
            float4 v = make_float4(0.f, 0.f, 0.f, 0.f);
            if (tok < B) v = *((const float4*)(feats + (size_t)tok*DDIM + ks2*64 + c4*4));
            __nv_bfloat16 h0,l0,h1,l1,h2,l2,h3,l3;
            split_bf16(v.x, h0, l0); split_bf16(v.y, h1, l1);
            split_bf16(v.z, h2, l2); split_bf16(v.w, h3, l3);
            __nv_bfloat16* dh = aH + row*K1_STR + c4*4;
            __nv_bfloat16* dl = aL + row*K1_STR + c4*4;
            dh[0]=h0; dh[1]=h1; dh[2]=h2; dh[3]=h3;
            dl[0]=l0; dl[1]=l1; dl[2]=l2; dl[3]=l3;
        }
        // stage W1 [64 k][64 j] fp32 -> hi/lo bf16
        #pragma unroll
        for (int i = 0; i < 4; i++) {
            int idx = tid + i*256;
            int row = idx >> 4, c4 = idx & 15;
            float4 v = *((const float4*)(W1 + (size_t)(ks2*64 + row)*64 + c4*4));
            __nv_bfloat16 h0,l0,h1,l1,h2,l2,h3,l3;
            split_bf16(v.x, h0, l0); split_bf16(v.y, h1, l1);
            split_bf16(v.z, h2, l2); split_bf16(v.w, h3, l3);
            __nv_bfloat16* dh = wH + row*K1_STR + c4*4;
            __nv_bfloat16* dl = wL + row*K1_STR + c4*4;
            dh[0]=h0; dh[1]=h1; dh[2]=h2; dh[3]=h3;
            dl[0]=l0; dl[1]=l1; dl[2]=l2; dl[3]=l3;
        }
        __syncthreads();

        // MMA over this 64-k half: warp = 16 tokens x 64 j
        #pragma unroll
        for (int ks = 0; ks < 4; ks++) {
            uint32_t arow = (uint32_t)(((wid*16 + (lane & 15)) * K1_STR
                              + ks*16 + ((lane >> 4) << 3)) * 2);
            uint32_t ah[4], al[4];
            ldsm_x4(ah, aH_s + arow);
            ldsm_x4(al, aL_s + arow);
            #pragma unroll
            for (int np = 0; np < 4; np++) {
                uint32_t brow = (uint32_t)(((ks*16 + (lane & 15)) * K1_STR
                                  + np*16 + ((lane >> 4) << 3)) * 2);
                uint32_t bh[4], bl[4];
                ldsm_x4_t(bh, wH_s + brow);
                ldsm_x4_t(bl, wL_s + brow);
                mma_bf16(acc[np*2],     ah, bh[0], bh[1]);
                mma_bf16(acc[np*2],     ah, bl[0], bl[1]);
                mma_bf16(acc[np*2],     al, bh[0], bh[1]);
                mma_bf16(acc[np*2 + 1], ah, bh[2], bh[3]);
                mma_bf16(acc[np*2 + 1], ah, bl[2], bl[3]);
                mma_bf16(acc[np*2 + 1], al, bh[2], bh[3]);
            }
        }
    }

    // epilogue: tanh, dot W2, quad reduce, exp
    float s0 = 0.f, s1 = 0.f;
    #pragma unroll
    for (int nt = 0; nt < 8; nt++) {
        int j0 = nt*8 + (lane & 3)*2;
        float b1a = __ldg(b1 + j0), b1b = __ldg(b1 + j0 + 1);
        float w2a = __ldg(W2 + j0), w2b = __ldg(W2 + j0 + 1);
        s0 += tanhf(acc[nt][0] + b1a) * w2a + tanhf(acc[nt][1] + b1b) * w2b;
        s1 += tanhf(acc[nt][2] + b1a) * w2a + tanhf(acc[nt][3] + b1b) * w2b;
    }
    #pragma unroll
    for (int m = 1; m <= 2; m <<= 1) {
        s0 += __shfl_xor_sync(0xffffffffu, s0, m);
        s1 += __shfl_xor_sync(0xffffffffu, s1, m);
    }
    if ((lane & 3) == 0) {
        float bb2 = __ldg(b2);
        int r = lane >> 2;
        int tok = tok0 + wid*16 + r;
        if (tok < B)     g_p[tok]     = expf(s0 + bb2);
        if (tok + 8 < B) g_p[tok + 8] = expf(s1 + bb2);
    }
}

// ---------------------------------------------------------------------------
// Kernel 2: split-K bf16 MMA: num[l,d] = sum_b mask[l,b] * (p[b]*f[b,d]),
// g split hi/lo, Z fused. Register double-buffering: chunk c+1's LDGs are
// issued before chunk c's MMA block so DRAM latency hides behind tensor work.
// grid = (2 l-tiles) x SPLITK, block = 256 thr = 8 warps, warp = 32 l x 64 d.
// ---------------------------------------------------------------------------
#define MA_STRIDE 72
#define G_STRIDE  136
#define SM2_BYTES (128*MA_STRIDE*2 + 2*(64*G_STRIDE*2) + 2048*4)

__global__ __launch_bounds__(256, 1) void k2_mma(
    const float* __restrict__ feats, const float* __restrict__ mask,
    int B, int chunksPerSplit)
{
    extern __shared__ char smraw[];
    __nv_bfloat16* mA = (__nv_bfloat16*)smraw;          // [128 l][72]
    __nv_bfloat16* gH = mA + 128*MA_STRIDE;             // [64 k][136]
    __nv_bfloat16* gL = gH + 64*G_STRIDE;               // [64 k][136]
    float*        zsm = (float*)(gL + 64*G_STRIDE);     // [2048]

    int tid  = threadIdx.x;
    int lt   = blockIdx.x;
    int y    = blockIdx.y;
    int l0   = lt * 128;
    int wid  = tid >> 5, lane = tid & 31;
    int wm   = wid & 3, wn = wid >> 2;

    float acc[2][8][4];
    #pragma unroll
    for (int mt = 0; mt < 2; mt++)
        #pragma unroll
        for (int nt = 0; nt < 8; nt++)
            #pragma unroll
            for (int e = 0; e < 4; e++) acc[mt][nt][e] = 0.f;
    float zacc8[8];
    #pragma unroll
    for (int i = 0; i < 8; i++) zacc8[i] = 0.f;

    uint32_t mA_s = (uint32_t)__cvta_generic_to_shared(mA);
    uint32_t gH_s = (uint32_t)__cvta_generic_to_shared(gH);
    uint32_t gL_s = (uint32_t)__cvta_generic_to_shared(gL);

    // register staging buffers (double buffer vs smem)
    float4 m4[8], f4[8];

    // prologue: load chunk 0
    {
        int kbase = (y * chunksPerSplit) * KCHUNK;
        #pragma unroll
        for (int i = 0; i < 8; i++) {
            int idx = tid + i*256;
            int row = idx >> 4, c4 = idx & 15;
            int gk = kbase + c4*4;
            m4[i] = (gk < B) ? *((const float4*)(mask + (size_t)(l0 + row)*B + gk))
                             : make_float4(0.f, 0.f, 0.f, 0.f);
        }
        #pragma unroll
        for (int i = 0; i < 8; i++) {
            int idx = tid + i*256;
            int row = idx >> 5, c4 = idx & 31;
            int tok = kbase + row;
            f4[i] = (tok < B) ? ((const float4*)(feats + (size_t)tok*DDIM))[c4]
                              : make_float4(0.f, 0.f, 0.f, 0.f);
        }
    }

    for (int c = 0; c < chunksPerSplit; c++) {
        int kbase = (y * chunksPerSplit + c) * KCHUNK;

        // ---- convert + store chunk c from registers; fuse Z partial ----
        #pragma unroll
        for (int i = 0; i < 8; i++) {
            int idx = tid + i*256;
            int row = idx >> 4, c4 = idx & 15;
            int gk = kbase + c4*4;
            float4 v = m4[i];
            float4 pv = (gk < B) ? *((const float4*)(g_p + gk))
                                 : make_float4(0.f, 0.f, 0.f, 0.f);
            zacc8[i] += v.x*pv.x + v.y*pv.y + v.z*pv.z + v.w*pv.w;
            __nv_bfloat16* dst = mA + row*MA_STRIDE + c4*4;
            *(__nv_bfloat162*)(dst)     = __floats2bfloat162_rn(v.x, v.y);
            *(__nv_bfloat162*)(dst + 2) = __floats2bfloat162_rn(v.z, v.w);
        }
        #pragma unroll
        for (int i = 0; i < 8; i++) {
            int idx = tid + i*256;
            int row = idx >> 5, c4 = idx & 31;
            int tok = kbase + row;
            float pk = (tok < B) ? g_p[tok] : 0.f;
            float4 v = f4[i];
            float gx = v.x*pk, gy = v.y*pk, gz = v.z*pk, gw = v.w*pk;
            __nv_bfloat16 hx,lx,hy,ly,hz,lz,hw,lw;
            split_bf16(gx, hx, lx); split_bf16(gy, hy, ly);
            split_bf16(gz, hz, lz); split_bf16(gw, hw, lw);
            __nv_bfloat16* dh = gH + row*G_STRIDE + c4*4;
            __nv_bfloat16* dl = gL + row*G_STRIDE + c4*4;
            dh[0]=hx; dh[1]=hy; dh[2]=hz; dh[3]=hw;
            dl[0]=lx; dl[1]=ly; dl[2]=lz; dl[3]=lw;
        }

        // ---- issue chunk c+1 LDGs (consumed after MMA -> latency hidden) ----
        if (c + 1 < chunksPerSplit) {
            int kb2 = kbase + KCHUNK;
            #pragma unroll
            for (int i = 0; i < 8; i++) {
                int idx = tid + i*256;
                int row = idx >> 4, c4 = idx & 15;
                int gk = kb2 + c4*4;
                m4[i] = (gk < B) ? *((const float4*)(mask + (size_t)(l0 + row)*B + gk))
                                 : make_float4(0.f, 0.f, 0.f, 0.f);
            }
            #pragma unroll
            for (int i = 0; i < 8; i++) {
                int idx = tid + i*256;
                int row = idx >> 5, c4 = idx & 31;
                int tok = kb2 + row;
                f4[i] = (tok < B) ? ((const float4*)(feats + (size_t)tok*DDIM))[c4]
                                  : make_float4(0.f, 0.f, 0.f, 0.f);
            }
        }
        __syncthreads();

        // ---- MMA over chunk c ----
        #pragma unroll
        for (int ks = 0; ks < 4; ks++) {
            uint32_t a[2][4];
            #pragma unroll
            for (int mt = 0; mt < 2; mt++) {
                uint32_t addr = mA_s + (uint32_t)(((wm*32 + mt*16 + (lane & 15)) * MA_STRIDE
                                 + ks*16 + ((lane >> 4) << 3)) * 2);
                ldsm_x4(a[mt], addr);
            }
            #pragma unroll
            for (int pl = 0; pl < 2; pl++) {
                uint32_t base = pl ? gL_s : gH_s;
                #pragma unroll
                for (int np = 0; np < 4; np++) {
                    uint32_t b[4];
                    uint32_t addr = base + (uint32_t)(((ks*16 + (lane & 15)) * G_STRIDE
                                     + wn*64 + np*16 + ((lane >> 4) << 3)) * 2);
                    ldsm_x4_t(b, addr);
                    #pragma unroll
                    for (int mt = 0; mt < 2; mt++) {
                        mma_bf16(acc[mt][np*2],     a[mt], b[0], b[1]);
                        mma_bf16(acc[mt][np*2 + 1], a[mt], b[2], b[3]);
                    }
                }
            }
        }
        __syncthreads();
    }

    // ---- deterministic Z reduction ----
    #pragma unroll
    for (int i = 0; i < 8; i++) zsm[tid + i*256] = zacc8[i];
    __syncthreads();
    if (tid < 128) {
        float z = 0.f;
        #pragma unroll
        for (int j = 0; j < 16; j++) z += zsm[tid*16 + j];
        g_zpart[y*LTOT + l0 + tid] = z;
    }

    // ---- write numerator partials ----
    #pragma unroll
    for (int mt = 0; mt < 2; mt++) {
        #pragma unroll
        for (int nt = 0; nt < 8; nt++) {
            int grow = l0 + wm*32 + mt*16 + (lane >> 2);
            int gcol = wn*64 + nt*8 + (lane & 3)*2;
            size_t b0 = ((size_t)y*LTOT + grow) * DDIM + gcol;
            size_t b1 = ((size_t)y*LTOT + grow + 8) * DDIM + gcol;
            *(float2*)(g_part + b0) = make_float2(acc[mt][nt][0], acc[mt][nt][1]);
            *(float2*)(g_part + b1) = make_float2(acc[mt][nt][2], acc[mt][nt][3]);
        }
    }
}

// ---------------------------------------------------------------------------
// Kernel 3: reduce split-K partials, divide by Z, zero empty libraries
// ---------------------------------------------------------------------------
__global__ void k3_reduce(float* __restrict__ out)
{
    int l = blockIdx.x, d = threadIdx.x;
    float num = 0.f, z = 0.f;
    #pragma unroll 4
    for (int y = 0; y < SPLITK; y++) {
        num += g_part[((size_t)y*LTOT + l) * DDIM + d];
        z   += g_zpart[y*LTOT + l];
    }
    out[l*DDIM + d] = (z > 0.f) ? num / z : 0.f;
}

// ---------------------------------------------------------------------------
extern "C" void kernel_launch(void* const* d_in, const int* in_sizes, int n_in,
                              void* d_out, int out_size)
{
    const float* feats = (const float*)d_in[0];
    const float* mask  = (const float*)d_in[1];
    const float* W1    = (const float*)d_in[2];
    const float* b1    = (const float*)d_in[3];
    const float* W2    = (const float*)d_in[4];
    const float* b2    = (const float*)d_in[5];
    float* out = (float*)d_out;

    int B = in_sizes[0] / DDIM;           // 200000
    int totalChunks = (B + KCHUNK - 1) / KCHUNK;
    int cps = (totalChunks + SPLITK - 1) / SPLITK;

    cudaFuncSetAttribute(k1_logits, cudaFuncAttributeMaxDynamicSharedMemorySize, SM1_BYTES);
    cudaFuncSetAttribute(k2_mma,    cudaFuncAttributeMaxDynamicSharedMemorySize, SM2_BYTES);

    int g1 = (B + 127) / 128;
    k1_logits<<<g1, 256, SM1_BYTES>>>(feats, W1, b1, W2, b2, B);

    dim3 g2(LTOT / 128, SPLITK);
    k2_mma<<<g2, 256, SM2_BYTES>>>(feats, mask, B, cps);

    k3_reduce<<<LTOT, DDIM>>>(out);
}

// round 4
// speedup vs baseline: 3.0478x; 1.6384x over previous
#include <cuda_runtime.h>
#include <cuda_fp16.h>
#include <stdint.h>

#define SPLITK 148
#define KCHUNK 32
#define LTOT   256
#define DDIM   128

// scratch (allocation-free rule: __device__ globals)
__device__ float g_p[200064];                       // exp(logits) per token
__device__ float g_part[SPLITK * LTOT * DDIM];      // split-K partial numerators
__device__ float g_zpart[SPLITK * LTOT];            // split-K partial denominators

// ---------------------------------------------------------------------------
// MMA helpers (fp16 single plane)
// ---------------------------------------------------------------------------
__device__ __forceinline__ void ldsm_x4(uint32_t* r, uint32_t addr) {
    asm volatile("ldmatrix.sync.aligned.m8n8.x4.shared.b16 {%0,%1,%2,%3}, [%4];"
        : "=r"(r[0]), "=r"(r[1]), "=r"(r[2]), "=r"(r[3]) : "r"(addr));
}
__device__ __forceinline__ void ldsm_x4_t(uint32_t* r, uint32_t addr) {
    asm volatile("ldmatrix.sync.aligned.m8n8.x4.trans.shared.b16 {%0,%1,%2,%3}, [%4];"
        : "=r"(r[0]), "=r"(r[1]), "=r"(r[2]), "=r"(r[3]) : "r"(addr));
}
__device__ __forceinline__ void mma_fp16(float* c, const uint32_t* a, uint32_t b0, uint32_t b1) {
    asm volatile("mma.sync.aligned.m16n8k16.row.col.f32.f16.f16.f32 "
        "{%0,%1,%2,%3}, {%4,%5,%6,%7}, {%8,%9}, {%0,%1,%2,%3};"
        : "+f"(c[0]), "+f"(c[1]), "+f"(c[2]), "+f"(c[3])
        : "r"(a[0]), "r"(a[1]), "r"(a[2]), "r"(a[3]), "r"(b0), "r"(b1));
}
__device__ __forceinline__ void st_half4(__half* dst, float x, float y, float z, float w) {
    __half2 lo = __floats2half2_rn(x, y);
    __half2 hi = __floats2half2_rn(z, w);
    uint2 v;
    v.x = *(uint32_t*)&lo;
    v.y = *(uint32_t*)&hi;
    *(uint2*)dst = v;
}

// ---------------------------------------------------------------------------
// Kernel 1: p = exp(W2 . tanh(f @ W1 + b1) + b2), fp16 single-plane MMA.
// tile = 128 tokens, full K=128 staged once. warp = 16 tok x 64 j.
// ---------------------------------------------------------------------------
#define A1_STR 136   // 128 k + 8 pad (halves)
#define W1_STR 72    // 64 j + 8 pad (halves)
#define SM1_BYTES ((128*A1_STR + 128*W1_STR) * 2)

__global__ __launch_bounds__(256, 2) void k1_logits(
    const float* __restrict__ feats, const float* __restrict__ W1,
    const float* __restrict__ b1, const float* __restrict__ W2,
    const float* __restrict__ b2, int B)
{
    extern __shared__ __half sm1[];
    __half* aS = sm1;                  // [128 tok][136]
    __half* wS = sm1 + 128*A1_STR;     // [128 k][72]

    int tid = threadIdx.x;
    int tok0 = blockIdx.x * 128;
    int wid = tid >> 5, lane = tid & 31;

    // stage features [128 tok][128 k] fp32 -> fp16
    #pragma unroll
    for (int i = 0; i < 16; i++) {
        int idx = tid + i*256;
        int row = idx >> 5, c4 = idx & 31;
        int tok = tok0 + row;
        float4 v = make_float4(0.f, 0.f, 0.f, 0.f);
        if (tok < B) v = ((const float4*)(feats + (size_t)tok*DDIM))[c4];
        st_half4(aS + row*A1_STR + c4*4, v.x, v.y, v.z, v.w);
    }
    // stage W1 [128 k][64 j]
    #pragma unroll
    for (int i = 0; i < 8; i++) {
        int idx = tid + i*256;
        int row = idx >> 4, c4 = idx & 15;
        float4 v = ((const float4*)W1)[idx];
        st_half4(wS + row*W1_STR + c4*4, v.x, v.y, v.z, v.w);
    }
    __syncthreads();

    uint32_t aS_s = (uint32_t)__cvta_generic_to_shared(aS);
    uint32_t wS_s = (uint32_t)__cvta_generic_to_shared(wS);

    float acc[8][4];
    #pragma unroll
    for (int nt = 0; nt < 8; nt++)
        #pragma unroll
        for (int e = 0; e < 4; e++) acc[nt][e] = 0.f;

    #pragma unroll
    for (int ks = 0; ks < 8; ks++) {
        uint32_t a[4];
        ldsm_x4(a, aS_s + (uint32_t)(((wid*16 + (lane & 15)) * A1_STR
                          + ks*16 + ((lane >> 4) << 3)) * 2));
        #pragma unroll
        for (int np = 0; np < 4; np++) {
            uint32_t b[4];
            ldsm_x4_t(b, wS_s + (uint32_t)(((ks*16 + (lane & 15)) * W1_STR
                              + np*16 + ((lane >> 4) << 3)) * 2));
            mma_fp16(acc[np*2],     a, b[0], b[1]);
            mma_fp16(acc[np*2 + 1], a, b[2], b[3]);
        }
    }

    // epilogue: +b1, tanh, dot W2, quad reduce, exp
    float s0 = 0.f, s1 = 0.f;
    #pragma unroll
    for (int nt = 0; nt < 8; nt++) {
        int j0 = nt*8 + (lane & 3)*2;
        float b1a = __ldg(b1 + j0), b1b = __ldg(b1 + j0 + 1);
        float w2a = __ldg(W2 + j0), w2b = __ldg(W2 + j0 + 1);
        s0 += tanhf(acc[nt][0] + b1a) * w2a + tanhf(acc[nt][1] + b1b) * w2b;
        s1 += tanhf(acc[nt][2] + b1a) * w2a + tanhf(acc[nt][3] + b1b) * w2b;
    }
    #pragma unroll
    for (int m = 1; m <= 2; m <<= 1) {
        s0 += __shfl_xor_sync(0xffffffffu, s0, m);
        s1 += __shfl_xor_sync(0xffffffffu, s1, m);
    }
    if ((lane & 3) == 0) {
        float bb2 = __ldg(b2);
        int r = lane >> 2;
        int tok = tok0 + wid*16 + r;
        if (tok < B)     g_p[tok]     = expf(s0 + bb2);
        if (tok + 8 < B) g_p[tok + 8] = expf(s1 + bb2);
    }
}

// ---------------------------------------------------------------------------
// Kernel 2: split-K fp16 MMA: num[l,d] = sum_b mask[l,b]*(p[b]*f[b,d]).
// 2 CTAs/SM (one wave), KCHUNK=32, register prefetch + smem double buffer,
// ONE syncthreads per chunk. warp = 32 l x 64 d. Z fused into staging.
// ---------------------------------------------------------------------------
#define MA_STR 40    // 32 k + 8 pad (halves)
#define G_STR  136   // 128 d + 8 pad (halves)
#define MA_HALVES (128*MA_STR)   // 5120
#define G_HALVES  (32*G_STR)     // 4352
#define SM2_BYTES ((2*MA_HALVES + 2*G_HALVES) * 2 + 1024*4)

__global__ __launch_bounds__(256, 2) void k2_mma(
    const float* __restrict__ feats, const float* __restrict__ mask,
    int B, int chunksPerSplit)
{
    extern __shared__ char smraw[];
    __half* mA  = (__half*)smraw;                    // 2 x [128 l][40]
    __half* gS  = mA + 2*MA_HALVES;                  // 2 x [32 k][136]
    float*  zsm = (float*)(gS + 2*G_HALVES);         // [1024]

    int tid  = threadIdx.x;
    int lt   = blockIdx.x;
    int y    = blockIdx.y;
    int l0   = lt * 128;
    int wid  = tid >> 5, lane = tid & 31;
    int wm   = wid & 3, wn = wid >> 2;

    float acc[2][8][4];
    #pragma unroll
    for (int mt = 0; mt < 2; mt++)
        #pragma unroll
        for (int nt = 0; nt < 8; nt++)
            #pragma unroll
            for (int e = 0; e < 4; e++) acc[mt][nt][e] = 0.f;
    float zacc[4] = {0.f, 0.f, 0.f, 0.f};

    uint32_t mA_s = (uint32_t)__cvta_generic_to_shared(mA);
    uint32_t gS_s = (uint32_t)__cvta_generic_to_shared(gS);

    // prefetch registers
    float4 m4[4], f4[4];

    // staging index precompute
    int mrow = tid >> 3, mc4 = tid & 7;      // mask: rows mrow+32i, k-col mc4*4
    int frow = tid >> 5, fc4 = tid & 31;     // feats: k-rows frow+8i, d-col fc4*4

    // prologue: load chunk 0
    {
        int kbase = y * chunksPerSplit * KCHUNK;
        #pragma unroll
        for (int i = 0; i < 4; i++) {
            int gk = kbase + mc4*4;
            m4[i] = (gk < B) ? *((const float4*)(mask + (size_t)(l0 + mrow + i*32)*B + gk))
                             : make_float4(0.f, 0.f, 0.f, 0.f);
        }
        #pragma unroll
        for (int i = 0; i < 4; i++) {
            int tok = kbase + frow + i*8;
            f4[i] = (tok < B) ? ((const float4*)(feats + (size_t)tok*DDIM))[fc4]
                              : make_float4(0.f, 0.f, 0.f, 0.f);
        }
    }

    for (int c = 0; c < chunksPerSplit; c++) {
        int kbase = (y * chunksPerSplit + c) * KCHUNK;
        __half* mA_c = mA + (c & 1) * MA_HALVES;
        __half* gS_c = gS + (c & 1) * G_HALVES;

        // convert + store chunk c; fuse Z
        {
            int gk = kbase + mc4*4;
            float4 pv = (gk < B) ? *((const float4*)(g_p + gk))
                                 : make_float4(0.f, 0.f, 0.f, 0.f);
            #pragma unroll
            for (int i = 0; i < 4; i++) {
                float4 v = m4[i];
                zacc[i] += v.x*pv.x + v.y*pv.y + v.z*pv.z + v.w*pv.w;
                st_half4(mA_c + (mrow + i*32)*MA_STR + mc4*4, v.x, v.y, v.z, v.w);
            }
        }
        #pragma unroll
        for (int i = 0; i < 4; i++) {
            int tok = kbase + frow + i*8;
            float pk = (tok < B) ? g_p[tok] : 0.f;
            float4 v = f4[i];
            st_half4(gS_c + (frow + i*8)*G_STR + fc4*4, v.x*pk, v.y*pk, v.z*pk, v.w*pk);
        }

        // prefetch chunk c+1
        if (c + 1 < chunksPerSplit) {
            int kb2 = kbase + KCHUNK;
            #pragma unroll
            for (int i = 0; i < 4; i++) {
                int gk = kb2 + mc4*4;
                m4[i] = (gk < B) ? *((const float4*)(mask + (size_t)(l0 + mrow + i*32)*B + gk))
                                 : make_float4(0.f, 0.f, 0.f, 0.f);
            }
            #pragma unroll
            for (int i = 0; i < 4; i++) {
                int tok = kb2 + frow + i*8;
                f4[i] = (tok < B) ? ((const float4*)(feats + (size_t)tok*DDIM))[fc4]
                                  : make_float4(0.f, 0.f, 0.f, 0.f);
            }
        }
        __syncthreads();

        // MMA over chunk c (buffer c&1; WAR vs chunk c-2 covered by c-1's sync)
        uint32_t mA_b = mA_s + (uint32_t)((c & 1) * MA_HALVES * 2);
        uint32_t gS_b = gS_s + (uint32_t)((c & 1) * G_HALVES * 2);
        #pragma unroll
        for (int ks = 0; ks < 2; ks++) {
            uint32_t a[2][4];
            #pragma unroll
            for (int mt = 0; mt < 2; mt++)
                ldsm_x4(a[mt], mA_b + (uint32_t)(((wm*32 + mt*16 + (lane & 15)) * MA_STR
                                 + ks*16 + ((lane >> 4) << 3)) * 2));
            #pragma unroll
            for (int np = 0; np < 4; np++) {
                uint32_t b[4];
                ldsm_x4_t(b, gS_b + (uint32_t)(((ks*16 + (lane & 15)) * G_STR
                                 + wn*64 + np*16 + ((lane >> 4) << 3)) * 2));
                #pragma unroll
                for (int mt = 0; mt < 2; mt++) {
                    mma_fp16(acc[mt][np*2],     a[mt], b[0], b[1]);
                    mma_fp16(acc[mt][np*2 + 1], a[mt], b[2], b[3]);
                }
            }
        }
    }

    // deterministic Z reduction: zsm[row][8 k-cols]
    __syncthreads();
    #pragma unroll
    for (int i = 0; i < 4; i++)
        zsm[(mrow + i*32)*8 + mc4] = zacc[i];
    __syncthreads();
    if (tid < 128) {
        float z = 0.f;
        #pragma unroll
        for (int j = 0; j < 8; j++) z += zsm[tid*8 + j];
        g_zpart[y*LTOT + l0 + tid] = z;
    }

    // write numerator partials
    #pragma unroll
    for (int mt = 0; mt < 2; mt++) {
        #pragma unroll
        for (int nt = 0; nt < 8; nt++) {
            int grow = l0 + wm*32 + mt*16 + (lane >> 2);
            int gcol = wn*64 + nt*8 + (lane & 3)*2;
            size_t b0 = ((size_t)y*LTOT + grow) * DDIM + gcol;
            size_t b1 = ((size_t)y*LTOT + grow + 8) * DDIM + gcol;
            *(float2*)(g_part + b0) = make_float2(acc[mt][nt][0], acc[mt][nt][1]);
            *(float2*)(g_part + b1) = make_float2(acc[mt][nt][2], acc[mt][nt][3]);
        }
    }
}

// ---------------------------------------------------------------------------
// Kernel 3: reduce split-K partials, divide by Z, zero empty libraries
// ---------------------------------------------------------------------------
__global__ void k3_reduce(float* __restrict__ out)
{
    int l = blockIdx.x, d = threadIdx.x;
    float num = 0.f, z = 0.f;
    #pragma unroll 4
    for (int y = 0; y < SPLITK; y++) {
        num += g_part[((size_t)y*LTOT + l) * DDIM + d];
        z   += g_zpart[y*LTOT + l];
    }
    out[l*DDIM + d] = (z > 0.f) ? num / z : 0.f;
}

// ---------------------------------------------------------------------------
extern "C" void kernel_launch(void* const* d_in, const int* in_sizes, int n_in,
                              void* d_out, int out_size)
{
    const float* feats = (const float*)d_in[0];
    const float* mask  = (const float*)d_in[1];
    const float* W1    = (const float*)d_in[2];
    const float* b1    = (const float*)d_in[3];
    const float* W2    = (const float*)d_in[4];
    const float* b2    = (const float*)d_in[5];
    float* out = (float*)d_out;

    int B = in_sizes[0] / DDIM;           // 200000
    int totalChunks = (B + KCHUNK - 1) / KCHUNK;
    int cps = (totalChunks + SPLITK - 1) / SPLITK;

    cudaFuncSetAttribute(k1_logits, cudaFuncAttributeMaxDynamicSharedMemorySize, SM1_BYTES);
    cudaFuncSetAttribute(k2_mma,    cudaFuncAttributeMaxDynamicSharedMemorySize, SM2_BYTES);

    int g1 = (B + 127) / 128;
    k1_logits<<<g1, 256, SM1_BYTES>>>(feats, W1, b1, W2, b2, B);

    dim3 g2(LTOT / 128, SPLITK);
    k2_mma<<<g2, 256, SM2_BYTES>>>(feats, mask, B, cps);

    k3_reduce<<<LTOT, DDIM>>>(out);
}